// round 17
// baseline (speedup 1.0000x reference)
#include <cuda_runtime.h>
#include <cuda_fp16.h>
#include <cstdint>
#include <math.h>

#define MAIL   8
#define DMEM   128
#define DCAT   256
#define NPB    16
#define ROWS   128
#define NTHR   256

#define AH 264
#define MHH 136
#define QHS 72

#define OFF_NODE 0
#define OFF_TIME 64
#define OFF_BV   128
#define OFF_ATT  640
#define OFF_DT   1664
#define OFF_QB   2176
#define OFF_MEM  2304
#define OFF_OUT  10496
#define OFF_MH   18688
#define OFF_QH   23040
#define OFF_QK   27648
#define OFF_A    44544
#define SMEM_TOTAL 112128

__device__ __align__(16) uint32_t g_QKf[16384];
__device__ __align__(16) uint32_t g_VF[16384];
__device__ __align__(16) uint32_t g_WqF[8192];
__device__ __align__(16) uint32_t g_MlF[8192];

__device__ __forceinline__ uint32_t smem_u32(const void* p) {
    uint32_t a;
    asm("{ .reg .u64 t; cvta.to.shared.u64 t, %1; cvt.u32.u64 %0, t; }"
        : "=r"(a) : "l"(p));
    return a;
}
__device__ __forceinline__ void ldsm4(uint32_t addr, uint32_t& r0, uint32_t& r1,
                                      uint32_t& r2, uint32_t& r3) {
    asm volatile("ldmatrix.sync.aligned.m8n8.x4.shared.b16 {%0,%1,%2,%3}, [%4];"
                 : "=r"(r0), "=r"(r1), "=r"(r2), "=r"(r3) : "r"(addr));
}
__device__ __forceinline__ void ldsm4t(uint32_t addr, uint32_t& r0, uint32_t& r1,
                                       uint32_t& r2, uint32_t& r3) {
    asm volatile("ldmatrix.sync.aligned.m8n8.x4.trans.shared.b16 {%0,%1,%2,%3}, [%4];"
                 : "=r"(r0), "=r"(r1), "=r"(r2), "=r"(r3) : "r"(addr));
}
__device__ __forceinline__ void mma16816(float* c, uint32_t a0, uint32_t a1,
                                         uint32_t a2, uint32_t a3,
                                         uint32_t b0, uint32_t b1) {
    asm volatile("mma.sync.aligned.m16n8k16.row.col.f32.f16.f16.f32 "
                 "{%0,%1,%2,%3},{%4,%5,%6,%7},{%8,%9},{%0,%1,%2,%3};"
                 : "+f"(c[0]), "+f"(c[1]), "+f"(c[2]), "+f"(c[3])
                 : "r"(a0), "r"(a1), "r"(a2), "r"(a3), "r"(b0), "r"(b1));
}
__device__ __forceinline__ uint32_t pack_h2(float x, float y) {
    __half2 h = __halves2half2(__float2half_rn(x), __float2half_rn(y));
    return *(uint32_t*)&h;
}
__device__ __forceinline__ float fast_cos(float x) {
    if (fabsf(x) < 0.2f) return fmaf(-0.5f * x, x, 1.f);
    return __cosf(x);
}
#define BARX(id) asm volatile("bar.sync %0, %1;" :: "r"(id), "r"(128) : "memory")

__global__ void prep_weights(const float* __restrict__ wq,
                             const float* __restrict__ wk,
                             const float* __restrict__ wv,
                             const float* __restrict__ mlp) {
    int i = blockIdx.x * 256 + threadIdx.x;
    if (i < 16384) {
        int breg = i & 1;
        int lane = (i >> 1) & 31;
        int nt   = (i >> 6) & 7;
        int ks   = (i >> 9) & 3;
        int w    = (i >> 11) & 7;
        int h  = w >> 2;
        int nc = (w & 3) * 64;
        int kr = ks * 16 + breg * 8 + (lane & 3) * 2;
        int kp = nc + nt * 8 + (lane >> 2);
        g_QKf[i] = pack_h2(wk[(h * 64 + kr) * 256 + kp],
                           wk[(h * 64 + kr + 1) * 256 + kp]);
    } else if (i < 32768) {
        int jj = i - 16384;
        int breg = jj & 1, l = (jj >> 1) & 31;
        int nt = (jj >> 6) & 1, ks = (jj >> 7) & 15, w = (jj >> 11) & 7;
        int h = w >> 2, j = w & 3;
        int col = h * 64 + j * 16 + nt * 8 + (l >> 2);
        int k0  = ks * 16 + breg * 8 + (l & 3) * 2;
        g_VF[jj] = pack_h2(wv[col * 256 + k0], wv[col * 256 + k0 + 1]);
    } else if (i < 49152) {
        int j = i - 32768;
        const float* W = (j < 8192) ? wq : mlp;
        int jj = j & 8191;
        int breg = jj & 1, l = (jj >> 1) & 31;
        int nt = (jj >> 6) & 1, ks = (jj >> 7) & 7, w = (jj >> 10) & 7;
        int col = w * 16 + nt * 8 + (l >> 2);
        int k0  = ks * 16 + breg * 8 + (l & 3) * 2;
        uint32_t v = pack_h2(W[col * 128 + k0], W[col * 128 + k0 + 1]);
        if (j < 8192) g_WqF[jj] = v; else g_MlF[jj] = v;
    }
}

__global__ __launch_bounds__(NTHR, 2)
void attn_mma_kernel(
    const int*   __restrict__ nodes,
    const float* __restrict__ times,
    const float* __restrict__ mem,
    const float* __restrict__ mail,
    const float* __restrict__ mail_time,
    const float* __restrict__ time_w,
    const float* __restrict__ time_b,
    const float* __restrict__ wq_b,
    const float* __restrict__ wk_b,
    const float* __restrict__ wv_b,
    const float* __restrict__ mlp_b,
    const float* __restrict__ ln_g,
    const float* __restrict__ ln_b,
    float*       __restrict__ out,
    int size)
{
    extern __shared__ __align__(1024) char smem[];
    const uint32_t sb = smem_u32(smem);
    const int tid = threadIdx.x, warp = tid >> 5, lane = tid & 31;
    const int base = blockIdx.x * NPB;

    int*   s_node = (int*)(smem + OFF_NODE);
    float* s_time = (float*)(smem + OFF_TIME);
    float* s_bv   = (float*)(smem + OFF_BV);
    float* s_att  = (float*)(smem + OFF_ATT);
    float* s_dt   = (float*)(smem + OFF_DT);
    float* s_qb   = (float*)(smem + OFF_QB);
    float* s_memf = (float*)(smem + OFF_MEM);
    float* s_out  = (float*)(smem + OFF_OUT);

    if (tid < NPB) {
        int g = base + tid; if (g >= size) g = size - 1;
        s_node[tid] = nodes[g];
        s_time[tid] = times[g];
    }
    if (tid >= 32 && tid < 64) s_qb[tid - 32] = 0.f;
    if (tid >= 224) s_bv[tid - 224] = wv_b[tid - 224];        // warp 7 loads 32
    if (tid >= 128 && tid < 224) s_bv[tid - 96] = wv_b[tid - 96]; // fills 32..127
    if (tid >= 64 && tid < 96) s_bv[tid - 64] = wv_b[tid - 64];   // fills 0..31
    __syncthreads();

    const int g8 = lane >> 3, lr = lane & 7;
    const uint32_t mrow = lr + ((g8 & 1) << 3);
    const uint32_t mko  = (uint32_t)((g8 >> 1) << 3);
    const uint32_t mHa  = sb + OFF_MH + (mrow * MHH + mko) * 2;
    const int r4 = lane >> 2, cpos = 2 * (lane & 3);

    if (warp < 4) {
        // ===== compute group: mem gather -> Q GEMM -> Qk GEMM =====
        #pragma unroll
        for (int t = 0; t < 4; t++) {
            int idx = tid + t * 128;
            int n = idx >> 5, c4 = (idx & 31) * 4;
            float4 v = *(const float4*)(mem + (size_t)s_node[n] * DMEM + c4);
            ((float4*)s_memf)[idx] = v;
            uint2 hv = { pack_h2(v.x, v.y), pack_h2(v.z, v.w) };
            *(uint2*)(smem + OFF_MH + (uint32_t)(n * MHH + c4) * 2) = hv;
        }
        BARX(1);

        // Q GEMM: warp w -> cols [w*32, w*32+32)
        {
            float qa[4][4];
            #pragma unroll
            for (int ct = 0; ct < 4; ct++)
                #pragma unroll
                for (int u = 0; u < 4; u++) qa[ct][u] = 0.f;
            const uint2* wq2 = (const uint2*)g_WqF;
            #pragma unroll
            for (int ks = 0; ks < 8; ks++) {
                uint32_t a0, a1, a2, a3;
                ldsm4(mHa + (uint32_t)ks * 32, a0, a1, a2, a3);
                #pragma unroll
                for (int ct = 0; ct < 4; ct++) {
                    int ow = 2 * warp + (ct >> 1);
                    uint2 b = __ldg(wq2 + (uint32_t)ow * 512 + ks * 64 + (ct & 1) * 32 + lane);
                    mma16816(qa[ct], a0, a1, a2, a3, b.x, b.y);
                }
            }
            const int h = warp >> 1;
            float cA = 0.f, cB = 0.f;
            #pragma unroll
            for (int ct = 0; ct < 4; ct++) {
                int col = warp * 32 + ct * 8 + cpos;
                float b0 = __ldg(wq_b + col), b1 = __ldg(wq_b + col + 1);
                float q0 = qa[ct][0] + b0, q1 = qa[ct][1] + b1;
                float q2 = qa[ct][2] + b0, q3 = qa[ct][3] + b1;
                int cl = col & 63;
                *(uint32_t*)(smem + OFF_QH + ((uint32_t)(h * 16 + r4) * QHS + cl) * 2) =
                    pack_h2(q0, q1);
                *(uint32_t*)(smem + OFF_QH + ((uint32_t)(h * 16 + r4 + 8) * QHS + cl) * 2) =
                    pack_h2(q2, q3);
                float k0 = __ldg(wk_b + col), k1 = __ldg(wk_b + col + 1);
                cA = fmaf(q0, k0, fmaf(q1, k1, cA));
                cB = fmaf(q2, k0, fmaf(q3, k1, cB));
            }
            atomicAdd(&s_qb[r4 * 2 + h], cA);
            atomicAdd(&s_qb[(r4 + 8) * 2 + h], cB);
        }
        BARX(1);

        // Qk GEMM: warp w -> head h=w>>1, kappa chunks (w&1)*128 + {0,64}
        {
            const int h = warp >> 1;
            const uint32_t aQ = sb + OFF_QH + (((uint32_t)(h * 16) + mrow) * QHS + mko) * 2;
            #pragma unroll
            for (int c2 = 0; c2 < 2; c2++) {
                int nc = (warp & 1) * 128 + c2 * 64;
                int ow = h * 4 + (nc >> 6);
                float acc[8][4];
                #pragma unroll
                for (int t = 0; t < 8; t++)
                    #pragma unroll
                    for (int u = 0; u < 4; u++) acc[t][u] = 0.f;
                const uint2* wf = (const uint2*)g_QKf + (uint32_t)ow * 1024 + lane;
                #pragma unroll
                for (int ks = 0; ks < 4; ks++) {
                    uint32_t a0, a1, a2, a3;
                    ldsm4(aQ + (uint32_t)ks * 32, a0, a1, a2, a3);
                    #pragma unroll
                    for (int nt = 0; nt < 8; nt++) {
                        uint2 b = __ldg(wf + (ks * 8 + nt) * 32);
                        mma16816(acc[nt], a0, a1, a2, a3, b.x, b.y);
                    }
                }
                #pragma unroll
                for (int nt = 0; nt < 8; nt++) {
                    int k0 = nc + nt * 8 + cpos;
                    *(uint32_t*)(smem + OFF_QK + ((uint32_t)(r4 * 2 + h) * AH + k0) * 2) =
                        pack_h2(acc[nt][0], acc[nt][1]);
                    *(uint32_t*)(smem + OFF_QK + ((uint32_t)((r4 + 8) * 2 + h) * AH + k0) * 2) =
                        pack_h2(acc[nt][2], acc[nt][3]);
                }
            }
        }
    } else {
        // ===== build group: dt + mail -> time encode =====
        const int wg = tid - 128;
        s_dt[wg] = s_time[wg >> 3] -
                   __ldg(mail_time + (size_t)s_node[wg >> 3] * MAIL + (wg & 7));
        {
            const int c4 = (wg & 31) * 4;
            #pragma unroll
            for (int t = 0; t < 32; t++) {
                int r = (wg >> 5) + t * 4;
                int n = r >> 3, slot = r & 7;
                float4 mv = *(const float4*)(mail + ((size_t)s_node[n] * MAIL + slot) * 128 + c4);
                uint2 hv = { pack_h2(mv.x, mv.y), pack_h2(mv.z, mv.w) };
                *(uint2*)(smem + OFF_A + ((size_t)r * AH + c4) * 2) = hv;
            }
        }
        BARX(2);                                      // s_dt ready
        {
            const int j = (wg & 63) * 2;
            const float tw0 = __ldg(time_w + j), tw1 = __ldg(time_w + j + 1);
            const float tb0 = __ldg(time_b + j), tb1 = __ldg(time_b + j + 1);
            #pragma unroll
            for (int t = 0; t < 64; t++) {
                int r = (wg >> 6) + t * 2;
                float dt = s_dt[r];
                float v0 = fast_cos(fmaf(dt, tw0, tb0));
                float v1 = fast_cos(fmaf(dt, tw1, tb1));
                *(uint32_t*)(smem + OFF_A + ((size_t)r * AH + 128 + j) * 2) = pack_h2(v0, v1);
            }
        }
    }
    __syncthreads();                                  // A, QK, qb ready

    // ---- logits GEMM (+ parallel zero of attn tiles in dead QH region) ----
    {
        #pragma unroll
        for (int z = 0; z < 4; z++) {
            int idx = tid + z * NTHR;
            int row = idx >> 5, wrd = idx & 31;
            *(uint32_t*)(smem + OFF_QH + (uint32_t)row * QHS * 2 + (uint32_t)wrd * 4) = 0u;
        }
        const int t = warp >> 1;
        const uint32_t aL = sb + OFF_A + (((uint32_t)(warp * 16) + mrow) * AH + mko) * 2;
        const uint32_t bL = sb + OFF_QK +
            (((uint32_t)(8 * t + (lane & 7))) * AH + ((uint32_t)(lane >> 3) << 3)) * 2;
        float acc[4] = {0.f, 0.f, 0.f, 0.f};
        #pragma unroll
        for (int kp = 0; kp < 8; kp++) {
            uint32_t b0, b1, b2, b3;
            ldsm4(bL + (uint32_t)kp * 64, b0, b1, b2, b3);
            uint32_t a0, a1, a2, a3;
            ldsm4(aL + (uint32_t)kp * 64, a0, a1, a2, a3);
            mma16816(acc, a0, a1, a2, a3, b0, b1);
            ldsm4(aL + (uint32_t)kp * 64 + 32, a0, a1, a2, a3);
            mma16816(acc, a0, a1, a2, a3, b2, b3);
        }
        #pragma unroll
        for (int u = 0; u < 4; u++) {
            int row = (u >> 1) * 8 + r4;
            int colg = 8 * t + cpos + (u & 1);
            int n = colg >> 1, h2 = colg & 1;
            if (n == 2 * warp + (row >> 3)) {
                float v = acc[u] + s_qb[n * 2 + h2];
                v = (v >= 0.f) ? v : 0.2f * v;
                s_att[(n * 8 + (row & 7)) * 2 + h2] = v;
            }
        }
    }
    __syncthreads();

    // ---- softmax: writes ONLY its 4 nonzero tile words ----
    if (tid < 32) {
        int n = tid >> 1, h = tid & 1;
        float mx = -1e30f;
        #pragma unroll
        for (int s = 0; s < MAIL; s++) mx = fmaxf(mx, s_att[(n * 8 + s) * 2 + h]);
        float ex[MAIL], sum = 0.f;
        #pragma unroll
        for (int s = 0; s < MAIL; s++) { ex[s] = __expf(s_att[(n * 8 + s) * 2 + h] - mx); sum += ex[s]; }
        float inv = 1.f / sum;
        int t = n >> 3, rloc = (n & 7) * 2 + h;
        uint32_t rowB = (uint32_t)OFF_QH + (uint32_t)(t * 16 + rloc) * QHS * 2
                      + (uint32_t)(n & 7) * 16;
        #pragma unroll
        for (int w = 0; w < 4; w++) {
            int s2 = w * 2;
            *(uint32_t*)(smem + rowB + (uint32_t)w * 4) =
                pack_h2(ex[s2] * inv, ex[s2 + 1] * inv);
        }
    }
    __syncthreads();

    // ---- contraction via MMA: weighted[h*16+n, c] = attnTile @ Mcat ----
    {
        const int t = warp >> 2, cchunk = (warp & 3) * 64;
        const uint32_t aT = sb + OFF_QH +
            (((uint32_t)(t * 16 + (lane & 15))) * QHS + ((uint32_t)(lane >> 4) << 3)) * 2;
        const uint32_t bT = sb + OFF_A +
            (((uint32_t)(64 * t + (lane & 15))) * AH + (uint32_t)cchunk + ((uint32_t)(lane >> 4) << 3)) * 2;
        float acc[8][4];
        #pragma unroll
        for (int q = 0; q < 8; q++)
            #pragma unroll
            for (int u = 0; u < 4; u++) acc[q][u] = 0.f;
        #pragma unroll
        for (int ks = 0; ks < 4; ks++) {
            uint32_t a0, a1, a2, a3;
            ldsm4(aT + (uint32_t)ks * 32, a0, a1, a2, a3);
            #pragma unroll
            for (int nn2 = 0; nn2 < 4; nn2++) {
                uint32_t r0, r1, r2, r3;
                ldsm4t(bT + ((uint32_t)(ks * 16) * AH + (uint32_t)(nn2 * 16)) * 2,
                       r0, r1, r2, r3);
                mma16816(acc[nn2 * 2],     a0, a1, a2, a3, r0, r1);
                mma16816(acc[nn2 * 2 + 1], a0, a1, a2, a3, r2, r3);
            }
        }
        int n0 = 8 * t + (r4 >> 1), hh = r4 & 1;
        uint32_t ro0 = (uint32_t)(hh * 16 + n0) * AH * 2;
        uint32_t ro1 = (uint32_t)(hh * 16 + n0 + 4) * AH * 2;
        #pragma unroll
        for (int nn = 0; nn < 8; nn++) {
            uint32_t c2 = (uint32_t)(cchunk + nn * 8 + cpos) * 2;
            *(uint32_t*)(smem + OFF_A + ro0 + c2) = pack_h2(acc[nn][0], acc[nn][1]);
            *(uint32_t*)(smem + OFF_A + ro1 + c2) = pack_h2(acc[nn][2], acc[nn][3]);
        }
    }
    __syncthreads();

    // ---- V GEMM on contracted rows (software-pipelined B prefetch) ----
    {
        const int h = warp >> 2, j = warp & 3;
        const uint32_t aHi = sb + OFF_A + (((uint32_t)(h * 16) + mrow) * AH + mko) * 2;
        float qa0[4] = {0.f, 0.f, 0.f, 0.f}, qa1[4] = {0.f, 0.f, 0.f, 0.f};
        const uint2* wfv = (const uint2*)g_VF + (uint32_t)warp * 1024 + lane;
        uint2 b0 = __ldg(wfv);
        uint2 b1 = __ldg(wfv + 32);
        #pragma unroll
        for (int ks = 0; ks < 16; ks++) {
            uint2 nb0, nb1;
            if (ks < 15) {
                nb0 = __ldg(wfv + (ks + 1) * 64);
                nb1 = __ldg(wfv + (ks + 1) * 64 + 32);
            }
            uint32_t h0, h1, h2, h3;
            ldsm4(aHi + (uint32_t)ks * 32, h0, h1, h2, h3);
            mma16816(qa0, h0, h1, h2, h3, b0.x, b0.y);
            mma16816(qa1, h0, h1, h2, h3, b1.x, b1.y);
            b0 = nb0; b1 = nb1;
        }
        int col = h * 64 + j * 16 + cpos;
        #pragma unroll
        for (int half = 0; half < 2; half++) {
            int node = r4 + half * 8;
            float v0 = (half ? qa0[2] : qa0[0]) + s_bv[col]     + s_memf[node * 128 + col];
            float v1 = (half ? qa0[3] : qa0[1]) + s_bv[col + 1] + s_memf[node * 128 + col + 1];
            float v8 = (half ? qa1[2] : qa1[0]) + s_bv[col + 8] + s_memf[node * 128 + col + 8];
            float v9 = (half ? qa1[3] : qa1[1]) + s_bv[col + 9] + s_memf[node * 128 + col + 9];
            s_out[node * 128 + col]     = v0;
            s_out[node * 128 + col + 1] = v1;
            s_out[node * 128 + col + 8] = v8;
            s_out[node * 128 + col + 9] = v9;
        }
    }
    __syncthreads();

    // ---- LayerNorm: warp handles 2 nodes; writes hi fp16 into MH ----
    #pragma unroll
    for (int t = 0; t < 2; t++) {
        int n = warp * 2 + t;
        float4 x4 = ((float4*)(s_out + n * 128))[lane];
        float sum = x4.x + x4.y + x4.z + x4.w;
        float sq  = fmaf(x4.x, x4.x, fmaf(x4.y, x4.y, fmaf(x4.z, x4.z, x4.w * x4.w)));
        #pragma unroll
        for (int off = 16; off; off >>= 1) {
            sum += __shfl_xor_sync(0xffffffffu, sum, off);
            sq  += __shfl_xor_sync(0xffffffffu, sq, off);
        }
        float mu = sum * (1.f / 128.f);
        float rstd = rsqrtf(sq * (1.f / 128.f) - mu * mu + 1e-5f);
        float o[4] = {x4.x, x4.y, x4.z, x4.w};
        float y[4];
        #pragma unroll
        for (int u = 0; u < 4; u++) {
            int cc = lane * 4 + u;
            y[u] = (o[u] - mu) * rstd * __ldg(ln_g + cc) + __ldg(ln_b + cc);
        }
        uint2 hv = { pack_h2(y[0], y[1]), pack_h2(y[2], y[3]) };
        *(uint2*)(smem + OFF_MH + (uint32_t)(n * MHH + lane * 4) * 2) = hv;
    }
    __syncthreads();

    // ---- MLP via MMA + ReLU + store (pipelined B prefetch) ----
    {
        float qa0[4] = {0.f, 0.f, 0.f, 0.f}, qa1[4] = {0.f, 0.f, 0.f, 0.f};
        const uint2* wfm = (const uint2*)g_MlF + (uint32_t)warp * 512 + lane;
        uint2 p0 = __ldg(wfm);
        uint2 p1 = __ldg(wfm + 32);
        #pragma unroll
        for (int ks = 0; ks < 8; ks++) {
            uint2 n0, n1;
            if (ks < 7) { n0 = __ldg(wfm + (ks + 1) * 64); n1 = __ldg(wfm + (ks + 1) * 64 + 32); }
            uint32_t ah0, ah1, ah2, ah3;
            ldsm4(mHa + (uint32_t)ks * 32, ah0, ah1, ah2, ah3);
            mma16816(qa0, ah0, ah1, ah2, ah3, p0.x, p0.y);
            mma16816(qa1, ah0, ah1, ah2, ah3, p1.x, p1.y);
            p0 = n0; p1 = n1;
        }
        int col = warp * 16 + cpos;
        float b0 = __ldg(mlp_b + col),     b1 = __ldg(mlp_b + col + 1);
        float b8 = __ldg(mlp_b + col + 8), b9 = __ldg(mlp_b + col + 9);
        int g0 = base + r4, g1 = base + r4 + 8;
        if (g0 < size) {
            float2 v0 = { fmaxf(qa0[0] + b0, 0.f), fmaxf(qa0[1] + b1, 0.f) };
            float2 v1 = { fmaxf(qa1[0] + b8, 0.f), fmaxf(qa1[1] + b9, 0.f) };
            *(float2*)(out + (size_t)g0 * 128 + col)     = v0;
            *(float2*)(out + (size_t)g0 * 128 + col + 8) = v1;
        }
        if (g1 < size) {
            float2 v0 = { fmaxf(qa0[2] + b0, 0.f), fmaxf(qa0[3] + b1, 0.f) };
            float2 v1 = { fmaxf(qa1[2] + b8, 0.f), fmaxf(qa1[3] + b9, 0.f) };
            *(float2*)(out + (size_t)g1 * 128 + col)     = v0;
            *(float2*)(out + (size_t)g1 * 128 + col + 8) = v1;
        }
    }
}

extern "C" void kernel_launch(void* const* d_in, const int* in_sizes, int n_in,
                              void* d_out, int out_size) {
    const int*   nodes     = (const int*)  d_in[0];
    const float* times     = (const float*)d_in[1];
    const float* mem       = (const float*)d_in[2];
    const float* mail      = (const float*)d_in[3];
    const float* mail_time = (const float*)d_in[4];
    const float* time_w    = (const float*)d_in[5];
    const float* time_b    = (const float*)d_in[6];
    const float* wq_w      = (const float*)d_in[7];
    const float* wq_b      = (const float*)d_in[8];
    const float* wk_w      = (const float*)d_in[9];
    const float* wk_b      = (const float*)d_in[10];
    const float* wv_w      = (const float*)d_in[11];
    const float* wv_b      = (const float*)d_in[12];
    const float* mlp_w     = (const float*)d_in[13];
    const float* mlp_b     = (const float*)d_in[14];
    const float* ln_g      = (const float*)d_in[15];
    const float* ln_b      = (const float*)d_in[16];
    int size = in_sizes[0];

    cudaFuncSetAttribute(attn_mma_kernel,
                         cudaFuncAttributeMaxDynamicSharedMemorySize, SMEM_TOTAL);

    prep_weights<<<256, 256>>>(wq_w, wk_w, wv_w, mlp_w);

    int nblk = (size + NPB - 1) / NPB;
    attn_mma_kernel<<<nblk, NTHR, SMEM_TOTAL>>>(
        nodes, times, mem, mail, mail_time, time_w, time_b,
        wq_b, wk_b, wv_b, mlp_b, ln_g, ln_b,
        (float*)d_out, size);
}